// round 6
// baseline (speedup 1.0000x reference)
#include <cuda_runtime.h>
#include <cuda_bf16.h>
#include <cstdint>

#define DEVINL __device__ __forceinline__

// ---------------- problem dims ----------------
#define MTOK 16384   // B*S = 8*2048
#define DIN  4096
#define DOUT 4096

// ---------------- scratch (device globals; no allocs allowed) ----------------
__device__ int8_t g_xq[(size_t)MTOK * DIN];   // 64 MB quantized activations (int8)
__device__ int8_t g_wq[(size_t)DOUT * DIN];   // 16 MB ternary weights (int8)
__device__ float g_inv_scale[MTOK];           // per-token 1/(scale_x*scale_w)

// ---------------- PTX helpers (plain compute_103 only) ----------------
DEVINL uint32_t smem_u32(const void* p) {
    uint32_t a;
    asm("{ .reg .u64 t; cvta.to.shared.u64 t, %1; cvt.u32.u64 %0, t; }" : "=r"(a) : "l"(p));
    return a;
}
DEVINL void cp_async16(uint32_t dst, const void* src) {
    asm volatile("cp.async.cg.shared.global [%0], [%1], 16;" :: "r"(dst), "l"(src) : "memory");
}
DEVINL void cp_commit() { asm volatile("cp.async.commit_group;" ::: "memory"); }
template <int N>
DEVINL void cp_wait() { asm volatile("cp.async.wait_group %0;" :: "n"(N) : "memory"); }

DEVINL void ldsm_x4(uint32_t& r0, uint32_t& r1, uint32_t& r2, uint32_t& r3, uint32_t addr) {
    asm volatile("ldmatrix.sync.aligned.m8n8.x4.shared.b16 {%0,%1,%2,%3}, [%4];"
                 : "=r"(r0), "=r"(r1), "=r"(r2), "=r"(r3) : "r"(addr));
}
DEVINL void imma16832(int* d, const uint32_t* a, const uint32_t* b) {
    asm volatile(
        "mma.sync.aligned.m16n8k32.row.col.s32.s8.s8.s32 "
        "{%0,%1,%2,%3}, {%4,%5,%6,%7}, {%8,%9}, {%0,%1,%2,%3};"
        : "+r"(d[0]), "+r"(d[1]), "+r"(d[2]), "+r"(d[3])
        : "r"(a[0]), "r"(a[1]), "r"(a[2]), "r"(a[3]), "r"(b[0]), "r"(b[1]));
}

// ============================================================================
// Kernel 1: fused RMSNorm + per-token absmax quantization -> int8
// ============================================================================
__global__ __launch_bounds__(256) void quant_kernel(
    const float* __restrict__ x, const float* __restrict__ gamma,
    const float* __restrict__ scale_w)
{
    const int token = blockIdx.x;
    const int tid = threadIdx.x;
    const float4* xr = reinterpret_cast<const float4*>(x + (size_t)token * DIN);
    const float4* gr = reinterpret_cast<const float4*>(gamma);

    float4 v[4];
    float ss = 0.f;
#pragma unroll
    for (int i = 0; i < 4; ++i) {
        v[i] = xr[i * 256 + tid];
        ss += v[i].x * v[i].x + v[i].y * v[i].y + v[i].z * v[i].z + v[i].w * v[i].w;
    }
    __shared__ float red[8];
    __shared__ float redm[8];
#pragma unroll
    for (int o = 16; o; o >>= 1) ss += __shfl_xor_sync(~0u, ss, o);
    if ((tid & 31) == 0) red[tid >> 5] = ss;
    __syncthreads();
    float tot = 0.f;
#pragma unroll
    for (int i = 0; i < 8; ++i) tot += red[i];
    const float varg = tot * (1.0f / DIN) + 1e-5f;
    float rstd = rsqrtf(varg);
    rstd = rstd * (1.5f - 0.5f * varg * rstd * rstd);

    float xn[16];
    float amax = 0.f;
#pragma unroll
    for (int i = 0; i < 4; ++i) {
        float4 g = gr[i * 256 + tid];
        xn[i * 4 + 0] = v[i].x * rstd * g.x;
        xn[i * 4 + 1] = v[i].y * rstd * g.y;
        xn[i * 4 + 2] = v[i].z * rstd * g.z;
        xn[i * 4 + 3] = v[i].w * rstd * g.w;
#pragma unroll
        for (int j = 0; j < 4; ++j) amax = fmaxf(amax, fabsf(xn[i * 4 + j]));
    }
#pragma unroll
    for (int o = 16; o; o >>= 1) amax = fmaxf(amax, __shfl_xor_sync(~0u, amax, o));
    if ((tid & 31) == 0) redm[tid >> 5] = amax;
    __syncthreads();
    float am = 0.f;
#pragma unroll
    for (int i = 0; i < 8; ++i) am = fmaxf(am, redm[i]);
    const float sx = 127.0f / fmaxf(am, 1e-5f);

    uint32_t* oq = reinterpret_cast<uint32_t*>(g_xq + (size_t)token * DIN);
#pragma unroll
    for (int i = 0; i < 4; ++i) {
        int q[4];
#pragma unroll
        for (int j = 0; j < 4; ++j) {
            float r = rintf(xn[i * 4 + j] * sx);
            r = fminf(fmaxf(r, -128.f), 127.f);
            q[j] = (int)r;
        }
        uint32_t p = (uint32_t)(q[0] & 0xFF) | ((uint32_t)(q[1] & 0xFF) << 8) |
                     ((uint32_t)(q[2] & 0xFF) << 16) | ((uint32_t)(q[3] & 0xFF) << 24);
        oq[i * 256 + tid] = p;
    }
    if (tid == 0) g_inv_scale[token] = 1.0f / (sx * scale_w[0]);
}

// ============================================================================
// Kernel 2: ternary weight f32 {-1,0,1} -> int8
// ============================================================================
__global__ __launch_bounds__(256) void wconv_kernel(const float* __restrict__ w) {
    size_t i = (size_t)blockIdx.x * 256 + threadIdx.x;
    float4 v = reinterpret_cast<const float4*>(w)[i];
    int q0 = (int)v.x, q1 = (int)v.y, q2 = (int)v.z, q3 = (int)v.w;
    uint32_t p = (uint32_t)(q0 & 0xFF) | ((uint32_t)(q1 & 0xFF) << 8) |
                 ((uint32_t)(q2 & 0xFF) << 16) | ((uint32_t)(q3 & 0xFF) << 24);
    reinterpret_cast<uint32_t*>(g_wq)[i] = p;
}

// ============================================================================
// Kernel 3: int8 IMMA GEMM  out[m,n] = (xq . w^T)[m,n] * inv_scale[m] + bias[n]
// BM=128, BN=128, BK=128, 4-stage cp.async, ldmatrix + m16n8k32 s8.
// 8 warps: warp tile 64x32. No min-blocks bound => up to 255 regs, no spills.
// ============================================================================
#define BM 128
#define BN 128
#define BK 128
#define STAGES 4
#define ITERS (DIN / BK)                 // 32
#define TILE_BYTES (BM * BK)             // 16 KB
#define STAGE_BYTES (2 * TILE_BYTES)     // 32 KB (A + B)
#define SMEM_DYN_TOTAL (STAGES * STAGE_BYTES)  // 128 KB

__global__ __launch_bounds__(256)
void gemm_kernel(const float* __restrict__ bias, float* __restrict__ out)
{
    extern __shared__ __align__(1024) char smem[];
    const uint32_t sbase = smem_u32(smem);
    const int tid = threadIdx.x;
    const int wid = tid >> 5, lane = tid & 31;
    const int warp_m = wid >> 2;        // 0..1  (64 rows each)
    const int warp_n = wid & 3;         // 0..3  (32 cols each)
    const int tile_n = blockIdx.x;      // 0..31
    const int tile_m = blockIdx.y;      // 0..127

    const int8_t* Ag = g_xq + (size_t)tile_m * BM * DIN;
    const int8_t* Bg = g_wq + (size_t)tile_n * BN * DIN;

    // ---- hoisted cp.async addressing (A and B share the same layout) ----
    uint32_t soff[4];   // swizzled smem offsets within a tile
    uint32_t goff[4];   // global byte offsets within a k-chunk
#pragma unroll
    for (int i = 0; i < 4; ++i) {
        int c = tid + i * 256;
        int r = c >> 3, j = c & 7;
        soff[i] = (uint32_t)(r * 128) + (uint32_t)((j * 16) ^ ((r & 7) << 4));
        goff[i] = (uint32_t)(r * DIN + j * 16);
    }

    auto load_stage = [&](int it, int s) {
        const uint32_t sa = sbase + s * STAGE_BYTES;
        const int8_t* ap = Ag + it * BK;
        const int8_t* bp = Bg + it * BK;
#pragma unroll
        for (int i = 0; i < 4; ++i) cp_async16(sa + soff[i], ap + goff[i]);
#pragma unroll
        for (int i = 0; i < 4; ++i) cp_async16(sa + TILE_BYTES + soff[i], bp + goff[i]);
    };

    // ---- per-lane ldmatrix address components ----
    const int am = lane >> 3, ar = lane & 7;
    const uint32_t a_rowoff = (uint32_t)((warp_m * 64 + ((am & 1) << 3) + ar) * 128);
    const uint32_t a_bbase = (uint32_t)((am >> 1) * 16);
    const uint32_t a_xor = (uint32_t)(ar << 4);
    const uint32_t b_rowoff = (uint32_t)((warp_n * 32 + ((am >> 1) * 8) + ar) * 128);
    const uint32_t b_bbase = (uint32_t)((am & 1) * 16);
    const uint32_t b_xor = (uint32_t)(ar << 4);

    int accv[4][4][4];
#pragma unroll
    for (int mt = 0; mt < 4; ++mt)
#pragma unroll
        for (int nt = 0; nt < 4; ++nt)
#pragma unroll
            for (int q = 0; q < 4; ++q) accv[mt][nt][q] = 0;

    // ---- prologue: fill stages 0..2 ----
    load_stage(0, 0); cp_commit();
    load_stage(1, 1); cp_commit();
    load_stage(2, 2); cp_commit();

    for (int it = 0; it < ITERS; ++it) {
        cp_wait<2>();
        __syncthreads();
        if (it + 3 < ITERS) load_stage(it + 3, (it + 3) % STAGES);
        cp_commit();

        const uint32_t sa = sbase + (it % STAGES) * STAGE_BYTES;
        const uint32_t sb = sa + TILE_BYTES;
#pragma unroll
        for (int ks = 0; ks < 4; ++ks) {      // 4 x k32 per 128B chunk
            uint32_t a[4][4];
#pragma unroll
            for (int mt = 0; mt < 4; ++mt) {
                uint32_t addr = sa + a_rowoff + mt * (16 * 128) +
                                (((uint32_t)(ks * 32) + a_bbase) ^ a_xor);
                ldsm_x4(a[mt][0], a[mt][1], a[mt][2], a[mt][3], addr);
            }
            uint32_t b[4][2];
#pragma unroll
            for (int j = 0; j < 2; ++j) {
                uint32_t addr = sb + b_rowoff + j * (16 * 128) +
                                (((uint32_t)(ks * 32) + b_bbase) ^ b_xor);
                ldsm_x4(b[2 * j][0], b[2 * j][1], b[2 * j + 1][0], b[2 * j + 1][1], addr);
            }
#pragma unroll
            for (int mt = 0; mt < 4; ++mt)
#pragma unroll
                for (int nt = 0; nt < 4; ++nt)
                    imma16832(accv[mt][nt], a[mt], b[nt]);
        }
    }

    // ---- epilogue: s32 -> f32 * inv_scale[m] + bias[n] ----
    const int row0 = tile_m * BM + warp_m * 64 + (lane >> 2);
    const int col0 = tile_n * BN + warp_n * 32 + (lane & 3) * 2;
#pragma unroll
    for (int mt = 0; mt < 4; ++mt) {
        const int rlo = row0 + mt * 16;
        const float inv_lo = g_inv_scale[rlo];
        const float inv_hi = g_inv_scale[rlo + 8];
#pragma unroll
        for (int nt = 0; nt < 4; ++nt) {
            const int c = col0 + nt * 8;
            const float b0 = __ldg(bias + c);
            const float b1 = __ldg(bias + c + 1);
            float2 lo, hi;
            lo.x = (float)accv[mt][nt][0] * inv_lo + b0;
            lo.y = (float)accv[mt][nt][1] * inv_lo + b1;
            hi.x = (float)accv[mt][nt][2] * inv_hi + b0;
            hi.y = (float)accv[mt][nt][3] * inv_hi + b1;
            *reinterpret_cast<float2*>(out + (size_t)rlo * DOUT + c) = lo;
            *reinterpret_cast<float2*>(out + (size_t)(rlo + 8) * DOUT + c) = hi;
        }
    }
}

// ============================================================================
// launch
// ============================================================================
extern "C" void kernel_launch(void* const* d_in, const int* in_sizes, int n_in,
                              void* d_out, int out_size) {
    (void)in_sizes; (void)n_in; (void)out_size;
    const float* x       = (const float*)d_in[0];
    const float* w       = (const float*)d_in[1];
    const float* scale_w = (const float*)d_in[2];
    const float* gamma   = (const float*)d_in[3];
    const float* bias    = (const float*)d_in[4];
    float* out = (float*)d_out;

    cudaFuncSetAttribute(gemm_kernel, cudaFuncAttributeMaxDynamicSharedMemorySize, SMEM_DYN_TOTAL);

    quant_kernel<<<MTOK, 256>>>(x, gamma, scale_w);
    wconv_kernel<<<(int)((size_t)DOUT * DIN / 4 / 256), 256>>>(w);
    gemm_kernel<<<dim3(DOUT / BN, MTOK / BM), 256, SMEM_DYN_TOTAL>>>(bias, out);
}

// round 10
// speedup vs baseline: 1.0660x; 1.0660x over previous
#include <cuda_runtime.h>
#include <cuda_bf16.h>
#include <cstdint>

#define DEVINL __device__ __forceinline__

// ---------------- problem dims ----------------
#define MTOK 16384   // B*S = 8*2048
#define DIN  4096
#define DOUT 4096

// ---------------- scratch (device globals; no allocs allowed) ----------------
__device__ int8_t g_xq[(size_t)MTOK * DIN];   // 64 MB int8 activations
__device__ int8_t g_wq[(size_t)DOUT * DIN];   // 16 MB int8 ternary weights
__device__ float g_inv_scale[MTOK];           // per-token 1/(scale_x*scale_w)

// ---------------- PTX helpers (plain compute_103 only) ----------------
DEVINL uint32_t smem_u32(const void* p) {
    uint32_t a;
    asm("{ .reg .u64 t; cvta.to.shared.u64 t, %1; cvt.u32.u64 %0, t; }" : "=r"(a) : "l"(p));
    return a;
}
DEVINL void cp_async16(uint32_t dst, const void* src) {
    asm volatile("cp.async.cg.shared.global [%0], [%1], 16;" :: "r"(dst), "l"(src) : "memory");
}
DEVINL void cp_commit() { asm volatile("cp.async.commit_group;" ::: "memory"); }
template <int N>
DEVINL void cp_wait() { asm volatile("cp.async.wait_group %0;" :: "n"(N) : "memory"); }
DEVINL void ldsm_x4(uint32_t& r0, uint32_t& r1, uint32_t& r2, uint32_t& r3, uint32_t addr) {
    asm volatile("ldmatrix.sync.aligned.m8n8.x4.shared.b16 {%0,%1,%2,%3}, [%4];"
                 : "=r"(r0), "=r"(r1), "=r"(r2), "=r"(r3) : "r"(addr));
}
DEVINL void imma16832(int* d, const uint32_t* a, const uint32_t* b) {
    asm volatile(
        "mma.sync.aligned.m16n8k32.row.col.s32.s8.s8.s32 "
        "{%0,%1,%2,%3}, {%4,%5,%6,%7}, {%8,%9}, {%0,%1,%2,%3};"
        : "+r"(d[0]), "+r"(d[1]), "+r"(d[2]), "+r"(d[3])
        : "r"(a[0]), "r"(a[1]), "r"(a[2]), "r"(a[3]), "r"(b[0]), "r"(b[1]));
}

// ============================================================================
// Kernel 1: fused RMSNorm+quant (blocks 0..MTOK-1) and weight convert
// (blocks MTOK..MTOK+4095) -> int8 scratch.
// ============================================================================
#define WBLOCKS 4096
__global__ __launch_bounds__(256) void quant_fused_kernel(
    const float* __restrict__ x, const float* __restrict__ w,
    const float* __restrict__ gamma, const float* __restrict__ scale_w)
{
    const int tid = threadIdx.x;
    if (blockIdx.x >= MTOK) {
        // ---- weight convert: f32 {-1,0,1} -> int8 ----
        const int wb = blockIdx.x - MTOK;
        const float4* wr = reinterpret_cast<const float4*>(w);
#pragma unroll
        for (int i = 0; i < 4; ++i) {
            size_t g = (size_t)wb * 256 + tid + (size_t)i * (WBLOCKS * 256);  // group of 4
            float4 v = wr[g];
            int q0 = (int)v.x, q1 = (int)v.y, q2 = (int)v.z, q3 = (int)v.w;
            uint32_t p = (uint32_t)(q0 & 0xFF) | ((uint32_t)(q1 & 0xFF) << 8) |
                         ((uint32_t)(q2 & 0xFF) << 16) | ((uint32_t)(q3 & 0xFF) << 24);
            reinterpret_cast<uint32_t*>(g_wq)[g] = p;
        }
        return;
    }

    const int token = blockIdx.x;
    const float4* xr = reinterpret_cast<const float4*>(x + (size_t)token * DIN);
    const float4* gr = reinterpret_cast<const float4*>(gamma);

    float4 v[4];
    float ss = 0.f;
#pragma unroll
    for (int i = 0; i < 4; ++i) {
        v[i] = xr[i * 256 + tid];
        ss += v[i].x * v[i].x + v[i].y * v[i].y + v[i].z * v[i].z + v[i].w * v[i].w;
    }
    __shared__ float red[8];
    __shared__ float redm[8];
#pragma unroll
    for (int o = 16; o; o >>= 1) ss += __shfl_xor_sync(~0u, ss, o);
    if ((tid & 31) == 0) red[tid >> 5] = ss;
    __syncthreads();
    float tot = 0.f;
#pragma unroll
    for (int i = 0; i < 8; ++i) tot += red[i];
    const float varg = tot * (1.0f / DIN) + 1e-5f;
    float rstd = rsqrtf(varg);
    rstd = rstd * (1.5f - 0.5f * varg * rstd * rstd);

    float xn[16];
    float amax = 0.f;
#pragma unroll
    for (int i = 0; i < 4; ++i) {
        float4 g = gr[i * 256 + tid];
        xn[i * 4 + 0] = v[i].x * rstd * g.x;
        xn[i * 4 + 1] = v[i].y * rstd * g.y;
        xn[i * 4 + 2] = v[i].z * rstd * g.z;
        xn[i * 4 + 3] = v[i].w * rstd * g.w;
#pragma unroll
        for (int j = 0; j < 4; ++j) amax = fmaxf(amax, fabsf(xn[i * 4 + j]));
    }
#pragma unroll
    for (int o = 16; o; o >>= 1) amax = fmaxf(amax, __shfl_xor_sync(~0u, amax, o));
    if ((tid & 31) == 0) redm[tid >> 5] = amax;
    __syncthreads();
    float am = 0.f;
#pragma unroll
    for (int i = 0; i < 8; ++i) am = fmaxf(am, redm[i]);
    const float sx = 127.0f / fmaxf(am, 1e-5f);

    uint32_t* oq = reinterpret_cast<uint32_t*>(g_xq + (size_t)token * DIN);
#pragma unroll
    for (int i = 0; i < 4; ++i) {
        int q[4];
#pragma unroll
        for (int j = 0; j < 4; ++j) {
            float r = rintf(xn[i * 4 + j] * sx);
            r = fminf(fmaxf(r, -128.f), 127.f);
            q[j] = (int)r;
        }
        uint32_t p = (uint32_t)(q[0] & 0xFF) | ((uint32_t)(q[1] & 0xFF) << 8) |
                     ((uint32_t)(q[2] & 0xFF) << 16) | ((uint32_t)(q[3] & 0xFF) << 24);
        oq[i * 256 + tid] = p;
    }
    if (tid == 0) g_inv_scale[token] = 1.0f / (sx * scale_w[0]);
}

// ============================================================================
// Kernel 2: int8 IMMA GEMM (round-3 proven config)
// out[m,n] = (xq . w^T)[m,n] * inv_scale[m] + bias[n]
// BM=BN=BK=128, 3-stage cp.async, ldmatrix + m16n8k32 s8, occupancy 2.
// ============================================================================
#define BM 128
#define BN 128
#define BK 128
#define STAGES 3
#define ITERS (DIN / BK)                 // 32
#define TILE_BYTES (BM * BK)             // 16 KB
#define STAGE_BYTES (2 * TILE_BYTES)     // 32 KB (A + B)
#define SMEM_DYN_TOTAL (STAGES * STAGE_BYTES)  // 96 KB

__global__ __launch_bounds__(256, 2)
void gemm_imma_kernel(const float* __restrict__ bias, float* __restrict__ out)
{
    extern __shared__ __align__(1024) char smem[];
    const uint32_t sbase = smem_u32(smem);
    const int tid = threadIdx.x;
    const int wid = tid >> 5, lane = tid & 31;
    const int warp_m = wid >> 2;        // 0..1  (64 rows each)
    const int warp_n = wid & 3;         // 0..3  (32 cols each)
    const int tile_n = blockIdx.x;
    const int tile_m = blockIdx.y;

    const int8_t* Ag = g_xq + (size_t)tile_m * BM * DIN;
    const int8_t* Bg = g_wq + (size_t)tile_n * BN * DIN;

    auto load_stage = [&](int it, int s) {
        const uint32_t sa = sbase + s * STAGE_BYTES;
        const uint32_t sb = sa + TILE_BYTES;
        const int8_t* ap = Ag + (size_t)it * BK;
        const int8_t* bp = Bg + (size_t)it * BK;
#pragma unroll
        for (int i = 0; i < 4; ++i) {   // A: 1024 x 16B chunks / 256 threads
            int c = tid + i * 256;
            int r = c >> 3, j = c & 7;
            uint32_t off = (uint32_t)(r * 128) + (uint32_t)((j * 16) ^ ((r & 7) << 4));
            cp_async16(sa + off, ap + (size_t)r * DIN + j * 16);
        }
#pragma unroll
        for (int i = 0; i < 4; ++i) {   // B: same shape
            int c = tid + i * 256;
            int r = c >> 3, j = c & 7;
            uint32_t off = (uint32_t)(r * 128) + (uint32_t)((j * 16) ^ ((r & 7) << 4));
            cp_async16(sb + off, bp + (size_t)r * DIN + j * 16);
        }
    };

    const int am = lane >> 3, ar = lane & 7;
    const uint32_t a_rowoff = (uint32_t)((warp_m * 64 + ((am & 1) << 3) + ar) * 128);
    const uint32_t a_bbase = (uint32_t)((am >> 1) * 16);
    const uint32_t a_xor = (uint32_t)(ar << 4);
    const uint32_t b_rowoff = (uint32_t)((warp_n * 32 + ((am >> 1) * 8) + ar) * 128);
    const uint32_t b_bbase = (uint32_t)((am & 1) * 16);
    const uint32_t b_xor = (uint32_t)(ar << 4);

    int accv[4][4][4];
#pragma unroll
    for (int mt = 0; mt < 4; ++mt)
#pragma unroll
        for (int nt = 0; nt < 4; ++nt)
#pragma unroll
            for (int q = 0; q < 4; ++q) accv[mt][nt][q] = 0;

    load_stage(0, 0); cp_commit();
    load_stage(1, 1); cp_commit();

    for (int it = 0; it < ITERS; ++it) {
        cp_wait<1>();
        __syncthreads();
        if (it + 2 < ITERS) load_stage(it + 2, (it + 2) % STAGES);
        cp_commit();

        const uint32_t sa = sbase + (it % STAGES) * STAGE_BYTES;
        const uint32_t sb = sa + TILE_BYTES;
#pragma unroll
        for (int ks = 0; ks < 4; ++ks) {      // 4 x k32 per 128B tile
            uint32_t a[4][4];
#pragma unroll
            for (int mt = 0; mt < 4; ++mt) {
                uint32_t addr = sa + a_rowoff + mt * (16 * 128) +
                                (((uint32_t)(ks * 32) + a_bbase) ^ a_xor);
                ldsm_x4(a[mt][0], a[mt][1], a[mt][2], a[mt][3], addr);
            }
            uint32_t b[4][2];
#pragma unroll
            for (int jj = 0; jj < 2; ++jj) {  // each x4 covers n-tiles 2jj, 2jj+1
                uint32_t addr = sb + b_rowoff + jj * (16 * 128) +
                                (((uint32_t)(ks * 32) + b_bbase) ^ b_xor);
                ldsm_x4(b[2 * jj][0], b[2 * jj][1], b[2 * jj + 1][0], b[2 * jj + 1][1], addr);
            }
#pragma unroll
            for (int mt = 0; mt < 4; ++mt)
#pragma unroll
                for (int nt = 0; nt < 4; ++nt)
                    imma16832(accv[mt][nt], a[mt], b[nt]);
        }
    }

    // ---- epilogue: s32 -> f32 * inv_scale[m] + bias[n] ----
    const int row0 = tile_m * BM + warp_m * 64 + (lane >> 2);
    const int col0 = tile_n * BN + warp_n * 32 + (lane & 3) * 2;
#pragma unroll
    for (int mt = 0; mt < 4; ++mt) {
        const int rlo = row0 + mt * 16;
        const float inv_lo = g_inv_scale[rlo];
        const float inv_hi = g_inv_scale[rlo + 8];
#pragma unroll
        for (int nt = 0; nt < 4; ++nt) {
            const int c = col0 + nt * 8;
            const float b0 = __ldg(bias + c);
            const float b1 = __ldg(bias + c + 1);
            float2 lo, hi;
            lo.x = (float)accv[mt][nt][0] * inv_lo + b0;
            lo.y = (float)accv[mt][nt][1] * inv_lo + b1;
            hi.x = (float)accv[mt][nt][2] * inv_hi + b0;
            hi.y = (float)accv[mt][nt][3] * inv_hi + b1;
            *reinterpret_cast<float2*>(out + (size_t)rlo * DOUT + c) = lo;
            *reinterpret_cast<float2*>(out + (size_t)(rlo + 8) * DOUT + c) = hi;
        }
    }
}

// ============================================================================
// launch: two kernels per call -> ncu -s 5 -c 1 captures the GEMM (launch #6).
// ============================================================================
extern "C" void kernel_launch(void* const* d_in, const int* in_sizes, int n_in,
                              void* d_out, int out_size) {
    (void)in_sizes; (void)n_in; (void)out_size;
    const float* x       = (const float*)d_in[0];
    const float* w       = (const float*)d_in[1];
    const float* scale_w = (const float*)d_in[2];
    const float* gamma   = (const float*)d_in[3];
    const float* bias    = (const float*)d_in[4];
    float* out = (float*)d_out;

    cudaFuncSetAttribute(gemm_imma_kernel, cudaFuncAttributeMaxDynamicSharedMemorySize,
                         SMEM_DYN_TOTAL);

    quant_fused_kernel<<<MTOK + WBLOCKS, 256>>>(x, w, gamma, scale_w);
    gemm_imma_kernel<<<dim3(DOUT / BN, MTOK / BM), 256, SMEM_DYN_TOTAL>>>(bias, out);
}

// round 15
// speedup vs baseline: 1.2649x; 1.1866x over previous
#include <cuda_runtime.h>
#include <cuda_bf16.h>
#include <cstdint>

#define DEVINL __device__ __forceinline__

// ---------------- problem dims ----------------
#define MTOK 16384   // B*S = 8*2048
#define DIN  4096
#define DOUT 4096

// ---------------- scratch (device globals; no allocs allowed) ----------------
__device__ int8_t g_xq[(size_t)MTOK * DIN];   // 64 MB int8 activations
__device__ int8_t g_wq[(size_t)DOUT * DIN];   // 16 MB int8 ternary weights
__device__ float g_inv_scale[MTOK];           // per-token 1/(scale_x*scale_w)

// ---------------- PTX helpers ----------------
DEVINL uint32_t smem_u32(const void* p) {
    uint32_t a;
    asm("{ .reg .u64 t; cvta.to.shared.u64 t, %1; cvt.u32.u64 %0, t; }" : "=r"(a) : "l"(p));
    return a;
}
DEVINL void cp_async16(uint32_t dst, const void* src) {
    asm volatile("cp.async.cg.shared.global [%0], [%1], 16;" :: "r"(dst), "l"(src) : "memory");
}
DEVINL void cp_async4(uint32_t dst, const void* src) {
    asm volatile("cp.async.ca.shared.global [%0], [%1], 4;" :: "r"(dst), "l"(src) : "memory");
}
DEVINL void cp_commit() { asm volatile("cp.async.commit_group;" ::: "memory"); }
template <int N>
DEVINL void cp_wait() { asm volatile("cp.async.wait_group %0;" :: "n"(N) : "memory"); }
DEVINL void ldsm_x4(uint32_t& r0, uint32_t& r1, uint32_t& r2, uint32_t& r3, uint32_t addr) {
    asm volatile("ldmatrix.sync.aligned.m8n8.x4.shared.b16 {%0,%1,%2,%3}, [%4];"
                 : "=r"(r0), "=r"(r1), "=r"(r2), "=r"(r3) : "r"(addr));
}
DEVINL void imma16832(int* d, const uint32_t* a, const uint32_t* b) {
    asm volatile(
        "mma.sync.aligned.m16n8k32.row.col.s32.s8.s8.s32 "
        "{%0,%1,%2,%3}, {%4,%5,%6,%7}, {%8,%9}, {%0,%1,%2,%3};"
        : "+r"(d[0]), "+r"(d[1]), "+r"(d[2]), "+r"(d[3])
        : "r"(a[0]), "r"(a[1]), "r"(a[2]), "r"(a[3]), "r"(b[0]), "r"(b[1]));
}

// ============================================================================
// Kernel 1: fused RMSNorm+quant (blocks 0..MTOK-1) and weight convert
// (blocks MTOK..MTOK+4095) -> int8 scratch only.
// ============================================================================
#define WBLOCKS 4096
__global__ __launch_bounds__(256) void quant_fused_kernel(
    const float* __restrict__ x, const float* __restrict__ w,
    const float* __restrict__ gamma, const float* __restrict__ scale_w)
{
    const int tid = threadIdx.x;
    if (blockIdx.x >= MTOK) {
        const int wb = blockIdx.x - MTOK;
        const float4* wr = reinterpret_cast<const float4*>(w);
#pragma unroll
        for (int i = 0; i < 4; ++i) {
            size_t g = (size_t)wb * 256 + tid + (size_t)i * (WBLOCKS * 256);  // group of 4
            float4 v = wr[g];
            int q0 = (int)v.x, q1 = (int)v.y, q2 = (int)v.z, q3 = (int)v.w;
            uint32_t p = (uint32_t)(q0 & 0xFF) | ((uint32_t)(q1 & 0xFF) << 8) |
                         ((uint32_t)(q2 & 0xFF) << 16) | ((uint32_t)(q3 & 0xFF) << 24);
            reinterpret_cast<uint32_t*>(g_wq)[g] = p;
        }
        return;
    }

    const int token = blockIdx.x;
    const float4* xr = reinterpret_cast<const float4*>(x + (size_t)token * DIN);
    const float4* gr = reinterpret_cast<const float4*>(gamma);

    float4 v[4];
    float ss = 0.f;
#pragma unroll
    for (int i = 0; i < 4; ++i) {
        v[i] = xr[i * 256 + tid];
        ss += v[i].x * v[i].x + v[i].y * v[i].y + v[i].z * v[i].z + v[i].w * v[i].w;
    }
    __shared__ float red[8];
    __shared__ float redm[8];
#pragma unroll
    for (int o = 16; o; o >>= 1) ss += __shfl_xor_sync(~0u, ss, o);
    if ((tid & 31) == 0) red[tid >> 5] = ss;
    __syncthreads();
    float tot = 0.f;
#pragma unroll
    for (int i = 0; i < 8; ++i) tot += red[i];
    const float varg = tot * (1.0f / DIN) + 1e-5f;
    float rstd = rsqrtf(varg);
    rstd = rstd * (1.5f - 0.5f * varg * rstd * rstd);

    float xn[16];
    float amax = 0.f;
#pragma unroll
    for (int i = 0; i < 4; ++i) {
        float4 g = gr[i * 256 + tid];
        xn[i * 4 + 0] = v[i].x * rstd * g.x;
        xn[i * 4 + 1] = v[i].y * rstd * g.y;
        xn[i * 4 + 2] = v[i].z * rstd * g.z;
        xn[i * 4 + 3] = v[i].w * rstd * g.w;
#pragma unroll
        for (int j = 0; j < 4; ++j) amax = fmaxf(amax, fabsf(xn[i * 4 + j]));
    }
#pragma unroll
    for (int o = 16; o; o >>= 1) amax = fmaxf(amax, __shfl_xor_sync(~0u, amax, o));
    if ((tid & 31) == 0) redm[tid >> 5] = amax;
    __syncthreads();
    float am = 0.f;
#pragma unroll
    for (int i = 0; i < 8; ++i) am = fmaxf(am, redm[i]);
    const float sx = 127.0f / fmaxf(am, 1e-5f);

    uint32_t* oq = reinterpret_cast<uint32_t*>(g_xq + (size_t)token * DIN);
#pragma unroll
    for (int i = 0; i < 4; ++i) {
        int q[4];
#pragma unroll
        for (int j = 0; j < 4; ++j) {
            float r = rintf(xn[i * 4 + j] * sx);
            r = fminf(fmaxf(r, -128.f), 127.f);
            q[j] = (int)r;
        }
        uint32_t p = (uint32_t)(q[0] & 0xFF) | ((uint32_t)(q[1] & 0xFF) << 8) |
                     ((uint32_t)(q[2] & 0xFF) << 16) | ((uint32_t)(q[3] & 0xFF) << 24);
        oq[i * 256 + tid] = p;
    }
    if (tid == 0) g_inv_scale[token] = 1.0f / (sx * scale_w[0]);
}

// ============================================================================
// Kernel 2: HYBRID GEMM.
//   tile_n < IMMA_TILES  : proven IMMA mma.sync path (tensor pipe)
//   tile_n >= IMMA_TILES : dp4a path (fma pipe) — runs on the idle pipe of
//                          SMs whose other CTA is tensor-saturated.
// out[m,n] = (xq . w^T)[m,n] * inv_scale[m] + bias[n]; both paths exact s32.
// ============================================================================
#define BM 128
#define BN 128
#define BK 128
#define STAGES 3
#define ITERS (DIN / BK)                 // 32
#define TILE_BYTES (BM * BK)             // 16 KB
#define STAGE_BYTES (2 * TILE_BYTES)     // 32 KB (A + B)
#define SMEM_DYN_TOTAL (STAGES * STAGE_BYTES)  // 96 KB

#define IMMA_TILES 22                    // 22 imma tiles + 10 dp4a tiles (of 32)

// dp4a path constants
#define DKK 16                           // 16 u32 = 64 int8 per k-chunk
#define DSTRIDE 132                      // padded row stride in u32 (16B-aligned, low conflict)
#define DBUF_WORDS (DKK * DSTRIDE)       // 2112 u32 per tile buffer

__global__ __launch_bounds__(256, 2)
void gemm_hybrid_kernel(const float* __restrict__ bias, float* __restrict__ out)
{
    extern __shared__ __align__(1024) char smem[];
    const uint32_t sbase = smem_u32(smem);
    const int tid = threadIdx.x;
    const int tile_n = blockIdx.x;
    const int tile_m = blockIdx.y;

    if (tile_n < IMMA_TILES) {
        // ==================== IMMA path (round-10 proven) ====================
        const int wid = tid >> 5, lane = tid & 31;
        const int warp_m = wid >> 2;
        const int warp_n = wid & 3;

        const int8_t* Ag = g_xq + (size_t)tile_m * BM * DIN;
        const int8_t* Bg = g_wq + (size_t)tile_n * BN * DIN;

        auto load_stage = [&](int it, int s) {
            const uint32_t sa = sbase + s * STAGE_BYTES;
            const uint32_t sb = sa + TILE_BYTES;
            const int8_t* ap = Ag + (size_t)it * BK;
            const int8_t* bp = Bg + (size_t)it * BK;
#pragma unroll
            for (int i = 0; i < 4; ++i) {
                int c = tid + i * 256;
                int r = c >> 3, j = c & 7;
                uint32_t off = (uint32_t)(r * 128) + (uint32_t)((j * 16) ^ ((r & 7) << 4));
                cp_async16(sa + off, ap + (size_t)r * DIN + j * 16);
            }
#pragma unroll
            for (int i = 0; i < 4; ++i) {
                int c = tid + i * 256;
                int r = c >> 3, j = c & 7;
                uint32_t off = (uint32_t)(r * 128) + (uint32_t)((j * 16) ^ ((r & 7) << 4));
                cp_async16(sb + off, bp + (size_t)r * DIN + j * 16);
            }
        };

        const int am = lane >> 3, ar = lane & 7;
        const uint32_t a_rowoff = (uint32_t)((warp_m * 64 + ((am & 1) << 3) + ar) * 128);
        const uint32_t a_bbase = (uint32_t)((am >> 1) * 16);
        const uint32_t a_xor = (uint32_t)(ar << 4);
        const uint32_t b_rowoff = (uint32_t)((warp_n * 32 + ((am >> 1) * 8) + ar) * 128);
        const uint32_t b_bbase = (uint32_t)((am & 1) * 16);
        const uint32_t b_xor = (uint32_t)(ar << 4);

        int accv[4][4][4];
#pragma unroll
        for (int mt = 0; mt < 4; ++mt)
#pragma unroll
            for (int nt = 0; nt < 4; ++nt)
#pragma unroll
                for (int q = 0; q < 4; ++q) accv[mt][nt][q] = 0;

        load_stage(0, 0); cp_commit();
        load_stage(1, 1); cp_commit();

        for (int it = 0; it < ITERS; ++it) {
            cp_wait<1>();
            __syncthreads();
            if (it + 2 < ITERS) load_stage(it + 2, (it + 2) % STAGES);
            cp_commit();

            const uint32_t sa = sbase + (it % STAGES) * STAGE_BYTES;
            const uint32_t sb = sa + TILE_BYTES;
#pragma unroll
            for (int ks = 0; ks < 4; ++ks) {
                uint32_t a[4][4];
#pragma unroll
                for (int mt = 0; mt < 4; ++mt) {
                    uint32_t addr = sa + a_rowoff + mt * (16 * 128) +
                                    (((uint32_t)(ks * 32) + a_bbase) ^ a_xor);
                    ldsm_x4(a[mt][0], a[mt][1], a[mt][2], a[mt][3], addr);
                }
                uint32_t b[4][2];
#pragma unroll
                for (int jj = 0; jj < 2; ++jj) {
                    uint32_t addr = sb + b_rowoff + jj * (16 * 128) +
                                    (((uint32_t)(ks * 32) + b_bbase) ^ b_xor);
                    ldsm_x4(b[2 * jj][0], b[2 * jj][1], b[2 * jj + 1][0], b[2 * jj + 1][1], addr);
                }
#pragma unroll
                for (int mt = 0; mt < 4; ++mt)
#pragma unroll
                    for (int nt = 0; nt < 4; ++nt)
                        imma16832(accv[mt][nt], a[mt], b[nt]);
            }
        }

        const int row0 = tile_m * BM + warp_m * 64 + (lane >> 2);
        const int col0 = tile_n * BN + warp_n * 32 + (lane & 3) * 2;
#pragma unroll
        for (int mt = 0; mt < 4; ++mt) {
            const int rlo = row0 + mt * 16;
            const float inv_lo = g_inv_scale[rlo];
            const float inv_hi = g_inv_scale[rlo + 8];
#pragma unroll
            for (int nt = 0; nt < 4; ++nt) {
                const int c = col0 + nt * 8;
                const float b0 = __ldg(bias + c);
                const float b1 = __ldg(bias + c + 1);
                float2 lo, hi;
                lo.x = (float)accv[mt][nt][0] * inv_lo + b0;
                lo.y = (float)accv[mt][nt][1] * inv_lo + b1;
                hi.x = (float)accv[mt][nt][2] * inv_hi + b0;
                hi.y = (float)accv[mt][nt][3] * inv_hi + b1;
                *reinterpret_cast<float2*>(out + (size_t)rlo * DOUT + c) = lo;
                *reinterpret_cast<float2*>(out + (size_t)(rlo + 8) * DOUT + c) = hi;
            }
        }
    } else {
        // ==================== dp4a path (fma pipe) ====================
        // Thread grid 8x32: ty=tid>>5 (16-row group), tx=tid&31 (4-col group).
        // smem: k-major u32 tiles At/Bt[2][DKK][DSTRIDE], double-buffered.
        const int tx = tid & 31;
        const int ty = tid >> 5;

        uint32_t* s32 = reinterpret_cast<uint32_t*>(smem);
        // layout: A0 | A1 | B0 | B1, each DBUF_WORDS
        const uint32_t sA0 = sbase;
        const uint32_t sB0 = sbase + 2 * DBUF_WORDS * 4;

        const uint32_t* Ag = reinterpret_cast<const uint32_t*>(
            g_xq + (size_t)tile_m * BM * DIN);
        const uint32_t* Bg = reinterpret_cast<const uint32_t*>(
            g_wq + (size_t)tile_n * BN * DIN);
        (void)s32;

        // loader mapping: idx = p*256+tid => row=idx>>4 in 0..127, kk=idx&15
        const int l_kk = tid & 15;
        const int l_rb = tid >> 4;   // row base contribution (idx>>4 = p*16 + tid>>4)

        auto load_chunk = [&](int c, int buf) {
            const int c0 = c * DKK;   // u32 offset within row
            const uint32_t da = sA0 + (uint32_t)buf * DBUF_WORDS * 4;
            const uint32_t db = sB0 + (uint32_t)buf * DBUF_WORDS * 4;
#pragma unroll
            for (int p = 0; p < 8; ++p) {
                const int row = p * 16 + l_rb;
                const uint32_t soff = (uint32_t)(l_kk * DSTRIDE + row) * 4;
                cp_async4(da + soff, Ag + (size_t)row * (DIN / 4) + c0 + l_kk);
                cp_async4(db + soff, Bg + (size_t)row * (DIN / 4) + c0 + l_kk);
            }
        };

        int acc[16][4];
#pragma unroll
        for (int i = 0; i < 16; ++i)
#pragma unroll
            for (int j = 0; j < 4; ++j) acc[i][j] = 0;

        const int NCH = DIN / 64;   // 64 chunks
        load_chunk(0, 0); cp_commit();

        for (int c = 0; c < NCH; ++c) {
            if (c + 1 < NCH) load_chunk(c + 1, (c + 1) & 1);
            cp_commit();
            cp_wait<1>();
            __syncthreads();

            const uint32_t da = sA0 + (uint32_t)(c & 1) * DBUF_WORDS * 4;
            const uint32_t db = sB0 + (uint32_t)(c & 1) * DBUF_WORDS * 4;
#pragma unroll 1
            for (int kk = 0; kk < DKK; ++kk) {
                uint32_t a[16];
                uint32_t b[4];
                const uint32_t abase = da + (uint32_t)(kk * DSTRIDE + ty * 16) * 4;
                const uint32_t bbase = db + (uint32_t)(kk * DSTRIDE + tx * 4) * 4;
#pragma unroll
                for (int m4 = 0; m4 < 4; ++m4) {
                    uint4 t = *reinterpret_cast<const uint4*>(smem + (abase - sbase) + m4 * 16);
                    a[m4 * 4 + 0] = t.x; a[m4 * 4 + 1] = t.y;
                    a[m4 * 4 + 2] = t.z; a[m4 * 4 + 3] = t.w;
                }
                {
                    uint4 t = *reinterpret_cast<const uint4*>(smem + (bbase - sbase));
                    b[0] = t.x; b[1] = t.y; b[2] = t.z; b[3] = t.w;
                }
#pragma unroll
                for (int i = 0; i < 16; ++i)
#pragma unroll
                    for (int j = 0; j < 4; ++j)
                        acc[i][j] = __dp4a((int)a[i], (int)b[j], acc[i][j]);
            }
            __syncthreads();
        }

        // epilogue
        const int col0 = tile_n * BN + tx * 4;
        float4 bv;
        bv.x = __ldg(bias + col0 + 0);
        bv.y = __ldg(bias + col0 + 1);
        bv.z = __ldg(bias + col0 + 2);
        bv.w = __ldg(bias + col0 + 3);
#pragma unroll
        for (int i = 0; i < 16; ++i) {
            const int row = tile_m * BM + ty * 16 + i;
            const float inv = g_inv_scale[row];
            float4 r4;
            r4.x = (float)acc[i][0] * inv + bv.x;
            r4.y = (float)acc[i][1] * inv + bv.y;
            r4.z = (float)acc[i][2] * inv + bv.z;
            r4.w = (float)acc[i][3] * inv + bv.w;
            *reinterpret_cast<float4*>(out + (size_t)row * DOUT + col0) = r4;
        }
    }
}

// ============================================================================
// launch
// ============================================================================
extern "C" void kernel_launch(void* const* d_in, const int* in_sizes, int n_in,
                              void* d_out, int out_size) {
    (void)in_sizes; (void)n_in; (void)out_size;
    const float* x       = (const float*)d_in[0];
    const float* w       = (const float*)d_in[1];
    const float* scale_w = (const float*)d_in[2];
    const float* gamma   = (const float*)d_in[3];
    const float* bias    = (const float*)d_in[4];
    float* out = (float*)d_out;

    cudaFuncSetAttribute(gemm_hybrid_kernel, cudaFuncAttributeMaxDynamicSharedMemorySize,
                         SMEM_DYN_TOTAL);

    quant_fused_kernel<<<MTOK + WBLOCKS, 256>>>(x, w, gamma, scale_w);
    gemm_hybrid_kernel<<<dim3(DOUT / BN, MTOK / BM), 256, SMEM_DYN_TOTAL>>>(bias, out);
}

// round 16
// speedup vs baseline: 1.7333x; 1.3703x over previous
#include <cuda_runtime.h>
#include <cuda_bf16.h>
#include <cstdint>

#define DEVINL __device__ __forceinline__

// ---------------- problem dims ----------------
#define MTOK 16384   // B*S = 8*2048
#define DIN  4096
#define DOUT 4096

// ---------------- scratch (device globals; no allocs allowed) ----------------
__device__ int8_t g_xq[(size_t)MTOK * DIN];          // 64 MB int8 activations
__device__ int8_t g_wq[(size_t)DOUT * DIN];          // 16 MB int8 weights, row-major
__device__ uint32_t g_wqt[(size_t)(DIN / 4) * DOUT]; // 64 MB? no: (1024*4096)*4B = 16 MB, k-major packed
__device__ float g_inv_scale[MTOK];                  // per-token 1/(scale_x*scale_w)

// ---------------- PTX helpers ----------------
DEVINL uint32_t smem_u32(const void* p) {
    uint32_t a;
    asm("{ .reg .u64 t; cvta.to.shared.u64 t, %1; cvt.u32.u64 %0, t; }" : "=r"(a) : "l"(p));
    return a;
}
DEVINL void cp_async16(uint32_t dst, const void* src) {
    asm volatile("cp.async.cg.shared.global [%0], [%1], 16;" :: "r"(dst), "l"(src) : "memory");
}
DEVINL void cp_commit() { asm volatile("cp.async.commit_group;" ::: "memory"); }
template <int N>
DEVINL void cp_wait() { asm volatile("cp.async.wait_group %0;" :: "n"(N) : "memory"); }
DEVINL void ldsm_x4(uint32_t& r0, uint32_t& r1, uint32_t& r2, uint32_t& r3, uint32_t addr) {
    asm volatile("ldmatrix.sync.aligned.m8n8.x4.shared.b16 {%0,%1,%2,%3}, [%4];"
                 : "=r"(r0), "=r"(r1), "=r"(r2), "=r"(r3) : "r"(addr));
}
DEVINL void imma16832(int* d, const uint32_t* a, const uint32_t* b) {
    asm volatile(
        "mma.sync.aligned.m16n8k32.row.col.s32.s8.s8.s32 "
        "{%0,%1,%2,%3}, {%4,%5,%6,%7}, {%8,%9}, {%0,%1,%2,%3};"
        : "+r"(d[0]), "+r"(d[1]), "+r"(d[2]), "+r"(d[3])
        : "r"(a[0]), "r"(a[1]), "r"(a[2]), "r"(a[3]), "r"(b[0]), "r"(b[1]));
}

// ============================================================================
// Kernel 1: fused RMSNorm+quant (blocks 0..MTOK-1) and weight convert+transpose
// (blocks MTOK..MTOK+1023). Weight blocks produce g_wq (row-major) AND
// g_wqt (k-major u32 [DIN/4][DOUT]) via a coalesced smem-tile transpose.
// ============================================================================
#define WTBLOCKS 1024    // 64x64-word tiles over the 4096 x 1024-word matrix
__global__ __launch_bounds__(256) void quant_fused_kernel(
    const float* __restrict__ x, const float* __restrict__ w,
    const float* __restrict__ gamma, const float* __restrict__ scale_w)
{
    __shared__ uint32_t tbuf[64][65];
    const int tid = threadIdx.x;

    if (blockIdx.x >= MTOK) {
        // ---- weight tile: n in [n0,n0+64), kw in [kw0,kw0+64) (u32 words) ----
        const int wb = blockIdx.x - MTOK;
        const int n0 = (wb >> 4) * 64;
        const int kw0 = (wb & 15) * 64;
        const float4* wr = reinterpret_cast<const float4*>(w);
        uint32_t* wq32 = reinterpret_cast<uint32_t*>(g_wq);
#pragma unroll
        for (int i = 0; i < 16; ++i) {
            int c = tid + i * 256;            // 0..4095
            int row = c >> 6;                 // n offset 0..63
            int col = c & 63;                 // kw offset 0..63
            size_t g = (size_t)(n0 + row) * (DIN / 4) + kw0 + col;
            float4 v = wr[g];
            int q0 = (int)v.x, q1 = (int)v.y, q2 = (int)v.z, q3 = (int)v.w;
            uint32_t p = (uint32_t)(q0 & 0xFF) | ((uint32_t)(q1 & 0xFF) << 8) |
                         ((uint32_t)(q2 & 0xFF) << 16) | ((uint32_t)(q3 & 0xFF) << 24);
            wq32[g] = p;
            tbuf[row][col] = p;
        }
        __syncthreads();
#pragma unroll
        for (int i = 0; i < 4; ++i) {
            int c = tid + i * 256;            // 0..1023
            int kwr = c >> 4;                 // 0..63
            int nc = c & 15;                  // 0..15 (groups of 4 n)
            uint4 o;
            o.x = tbuf[nc * 4 + 0][kwr];
            o.y = tbuf[nc * 4 + 1][kwr];
            o.z = tbuf[nc * 4 + 2][kwr];
            o.w = tbuf[nc * 4 + 3][kwr];
            *reinterpret_cast<uint4*>(g_wqt + (size_t)(kw0 + kwr) * DOUT + n0 + nc * 4) = o;
        }
        return;
    }

    const int token = blockIdx.x;
    const float4* xr = reinterpret_cast<const float4*>(x + (size_t)token * DIN);
    const float4* gr = reinterpret_cast<const float4*>(gamma);

    float4 v[4];
    float ss = 0.f;
#pragma unroll
    for (int i = 0; i < 4; ++i) {
        v[i] = xr[i * 256 + tid];
        ss += v[i].x * v[i].x + v[i].y * v[i].y + v[i].z * v[i].z + v[i].w * v[i].w;
    }
    __shared__ float red[8];
    __shared__ float redm[8];
#pragma unroll
    for (int o = 16; o; o >>= 1) ss += __shfl_xor_sync(~0u, ss, o);
    if ((tid & 31) == 0) red[tid >> 5] = ss;
    __syncthreads();
    float tot = 0.f;
#pragma unroll
    for (int i = 0; i < 8; ++i) tot += red[i];
    const float varg = tot * (1.0f / DIN) + 1e-5f;
    float rstd = rsqrtf(varg);
    rstd = rstd * (1.5f - 0.5f * varg * rstd * rstd);

    float xn[16];
    float amax = 0.f;
#pragma unroll
    for (int i = 0; i < 4; ++i) {
        float4 g = gr[i * 256 + tid];
        xn[i * 4 + 0] = v[i].x * rstd * g.x;
        xn[i * 4 + 1] = v[i].y * rstd * g.y;
        xn[i * 4 + 2] = v[i].z * rstd * g.z;
        xn[i * 4 + 3] = v[i].w * rstd * g.w;
#pragma unroll
        for (int j = 0; j < 4; ++j) amax = fmaxf(amax, fabsf(xn[i * 4 + j]));
    }
#pragma unroll
    for (int o = 16; o; o >>= 1) amax = fmaxf(amax, __shfl_xor_sync(~0u, amax, o));
    if ((tid & 31) == 0) redm[tid >> 5] = amax;
    __syncthreads();
    float am = 0.f;
#pragma unroll
    for (int i = 0; i < 8; ++i) am = fmaxf(am, redm[i]);
    const float sx = 127.0f / fmaxf(am, 1e-5f);

    uint32_t* oq = reinterpret_cast<uint32_t*>(g_xq + (size_t)token * DIN);
#pragma unroll
    for (int i = 0; i < 4; ++i) {
        int q[4];
#pragma unroll
        for (int j = 0; j < 4; ++j) {
            float r = rintf(xn[i * 4 + j] * sx);
            r = fminf(fmaxf(r, -128.f), 127.f);
            q[j] = (int)r;
        }
        uint32_t p = (uint32_t)(q[0] & 0xFF) | ((uint32_t)(q[1] & 0xFF) << 8) |
                     ((uint32_t)(q[2] & 0xFF) << 16) | ((uint32_t)(q[3] & 0xFF) << 24);
        oq[i * 256 + tid] = p;
    }
    if (tid == 0) g_inv_scale[token] = 1.0f / (sx * scale_w[0]);
}

// ============================================================================
// Kernel 2: warp-fused HYBRID GEMM. Tile 128x128.
//   warps 0-3: IMMA (tensor pipe) -> output cols [0,64)
//   warps 4-7: dp4a (fma pipe)    -> output cols [64,128)
// Both pipes run on EVERY SM concurrently. Exact s32 math in both.
// ============================================================================
#define BM 128
#define BN 128
#define BK 128
#define STAGES 3
#define ITERS (DIN / BK)                 // 32
#define SA_BYTES (BM * 128)              // 16 KB A tile (swizzled row-major)
#define SBI_BYTES (64 * 128)             // 8 KB imma B rows 0..63 (swizzled)
#define SBD_PAD 68                       // u32 row stride (64 data + 4 pad)
#define SBD_BYTES (32 * SBD_PAD * 4)     // 8704 B dp4a B k-major [32 kw][64 n]
#define STAGE_BYTES (SA_BYTES + SBI_BYTES + SBD_BYTES)   // 33280
#define SMEM_DYN_TOTAL (STAGES * STAGE_BYTES)            // 99840

__global__ __launch_bounds__(256, 2)
void gemm_hybrid_kernel(const float* __restrict__ bias, float* __restrict__ out)
{
    extern __shared__ __align__(1024) char smem[];
    const uint32_t sbase = smem_u32(smem);
    const int tid = threadIdx.x;
    const int wid = tid >> 5, lane = tid & 31;
    const int tile_n = blockIdx.x;
    const int tile_m = blockIdx.y;

    const int8_t* Ag = g_xq + (size_t)tile_m * BM * DIN;
    const int8_t* Bg = g_wq + (size_t)tile_n * BN * DIN;          // rows 0..63 used
    const uint32_t* Wt = g_wqt + (size_t)0 * DOUT + tile_n * BN + 64;  // cols 64..127

    // loader: all 256 threads cover A (4x16B) + Bi (2x16B) + Bd (2x16B)
    auto load_stage = [&](int it, int s) {
        const uint32_t sa = sbase + s * STAGE_BYTES;
        const uint32_t sbi = sa + SA_BYTES;
        const uint32_t sbd = sbi + SBI_BYTES;
        const int8_t* ap = Ag + (size_t)it * BK;
        const int8_t* bp = Bg + (size_t)it * BK;
        const uint32_t* wp = Wt + (size_t)(it * 32) * DOUT;
#pragma unroll
        for (int i = 0; i < 4; ++i) {         // A: 1024 x 16B
            int c = tid + i * 256;
            int r = c >> 3, j = c & 7;
            uint32_t off = (uint32_t)(r * 128) + (uint32_t)((j * 16) ^ ((r & 7) << 4));
            cp_async16(sa + off, ap + (size_t)r * DIN + j * 16);
        }
#pragma unroll
        for (int i = 0; i < 2; ++i) {         // Bi: rows 0..63, 512 x 16B
            int c = tid + i * 256;
            int r = c >> 3, j = c & 7;
            uint32_t off = (uint32_t)(r * 128) + (uint32_t)((j * 16) ^ ((r & 7) << 4));
            cp_async16(sbi + off, bp + (size_t)r * DIN + j * 16);
        }
#pragma unroll
        for (int i = 0; i < 2; ++i) {         // Bd: 32 kw x 64 u32, 512 x 16B
            int c = tid + i * 256;
            int kw = c >> 4, cg = c & 15;
            cp_async16(sbd + (uint32_t)(kw * SBD_PAD * 4 + cg * 16),
                       wp + (size_t)kw * DOUT + cg * 4);
        }
    };

    if (wid < 4) {
        // ==================== IMMA path: cols [0,64) ====================
        const int warp_m = wid >> 1;    // 0..1  (64 rows each)
        const int warp_n = wid & 1;     // 0..1  (32 cols each)

        const int am = lane >> 3, ar = lane & 7;
        const uint32_t a_rowoff = (uint32_t)((warp_m * 64 + ((am & 1) << 3) + ar) * 128);
        const uint32_t a_bbase = (uint32_t)((am >> 1) * 16);
        const uint32_t a_xor = (uint32_t)(ar << 4);
        const uint32_t b_rowoff = (uint32_t)((warp_n * 32 + ((am >> 1) * 8) + ar) * 128);
        const uint32_t b_bbase = (uint32_t)((am & 1) * 16);
        const uint32_t b_xor = (uint32_t)(ar << 4);

        int accv[4][4][4];
#pragma unroll
        for (int mt = 0; mt < 4; ++mt)
#pragma unroll
            for (int nt = 0; nt < 4; ++nt)
#pragma unroll
                for (int q = 0; q < 4; ++q) accv[mt][nt][q] = 0;

        load_stage(0, 0); cp_commit();
        load_stage(1, 1); cp_commit();

        for (int it = 0; it < ITERS; ++it) {
            cp_wait<1>();
            __syncthreads();
            if (it + 2 < ITERS) load_stage(it + 2, (it + 2) % STAGES);
            cp_commit();

            const uint32_t sa = sbase + (it % STAGES) * STAGE_BYTES;
            const uint32_t sbi = sa + SA_BYTES;
#pragma unroll
            for (int ks = 0; ks < 4; ++ks) {
                uint32_t a[4][4];
#pragma unroll
                for (int mt = 0; mt < 4; ++mt) {
                    uint32_t addr = sa + a_rowoff + mt * (16 * 128) +
                                    (((uint32_t)(ks * 32) + a_bbase) ^ a_xor);
                    ldsm_x4(a[mt][0], a[mt][1], a[mt][2], a[mt][3], addr);
                }
                uint32_t b[4][2];
#pragma unroll
                for (int jj = 0; jj < 2; ++jj) {
                    uint32_t addr = sbi + b_rowoff + jj * (16 * 128) +
                                    (((uint32_t)(ks * 32) + b_bbase) ^ b_xor);
                    ldsm_x4(b[2 * jj][0], b[2 * jj][1], b[2 * jj + 1][0], b[2 * jj + 1][1], addr);
                }
#pragma unroll
                for (int mt = 0; mt < 4; ++mt)
#pragma unroll
                    for (int nt = 0; nt < 4; ++nt)
                        imma16832(accv[mt][nt], a[mt], b[nt]);
            }
        }

        const int row0 = tile_m * BM + warp_m * 64 + (lane >> 2);
        const int col0 = tile_n * BN + warp_n * 32 + (lane & 3) * 2;
#pragma unroll
        for (int mt = 0; mt < 4; ++mt) {
            const int rlo = row0 + mt * 16;
            const float inv_lo = g_inv_scale[rlo];
            const float inv_hi = g_inv_scale[rlo + 8];
#pragma unroll
            for (int nt = 0; nt < 4; ++nt) {
                const int c = col0 + nt * 8;
                const float b0 = __ldg(bias + c);
                const float b1 = __ldg(bias + c + 1);
                float2 lo, hi;
                lo.x = (float)accv[mt][nt][0] * inv_lo + b0;
                lo.y = (float)accv[mt][nt][1] * inv_lo + b1;
                hi.x = (float)accv[mt][nt][2] * inv_hi + b0;
                hi.y = (float)accv[mt][nt][3] * inv_hi + b1;
                *reinterpret_cast<float2*>(out + (size_t)rlo * DOUT + c) = lo;
                *reinterpret_cast<float2*>(out + (size_t)(rlo + 8) * DOUT + c) = hi;
            }
        }
    } else {
        // ==================== dp4a path: cols [64,128) ====================
        const int dtid = tid - 128;     // 0..127
        const int ry = dtid >> 4;       // 0..7  -> rows ry*16 .. +16
        const int cx = dtid & 15;       // 0..15 -> cols 64 + cx*4 .. +4

        int acc[16][4];
#pragma unroll
        for (int i = 0; i < 16; ++i)
#pragma unroll
            for (int j = 0; j < 4; ++j) acc[i][j] = 0;

        load_stage(0, 0); cp_commit();
        load_stage(1, 1); cp_commit();

        for (int it = 0; it < ITERS; ++it) {
            cp_wait<1>();
            __syncthreads();
            if (it + 2 < ITERS) load_stage(it + 2, (it + 2) % STAGES);
            cp_commit();

            const uint32_t soff = (it % STAGES) * STAGE_BYTES;
            const char* sa = smem + soff;
            const char* sbd = smem + soff + SA_BYTES + SBI_BYTES;
#pragma unroll 1
            for (int g = 0; g < 8; ++g) {
                uint4 b0 = *reinterpret_cast<const uint4*>(sbd + (4 * g + 0) * (SBD_PAD * 4) + cx * 16);
                uint4 b1 = *reinterpret_cast<const uint4*>(sbd + (4 * g + 1) * (SBD_PAD * 4) + cx * 16);
                uint4 b2 = *reinterpret_cast<const uint4*>(sbd + (4 * g + 2) * (SBD_PAD * 4) + cx * 16);
                uint4 b3 = *reinterpret_cast<const uint4*>(sbd + (4 * g + 3) * (SBD_PAD * 4) + cx * 16);
#pragma unroll
                for (int h = 0; h < 2; ++h) {
                    uint4 a[8];
#pragma unroll
                    for (int i = 0; i < 8; ++i) {
                        const int r = ry * 16 + h * 8 + i;
                        a[i] = *reinterpret_cast<const uint4*>(
                            sa + r * 128 + (((uint32_t)g ^ (uint32_t)i) << 4));
                    }
#pragma unroll
                    for (int i = 0; i < 8; ++i) {
                        const int rr = h * 8 + i;
                        acc[rr][0] = __dp4a((int)a[i].x, (int)b0.x, acc[rr][0]);
                        acc[rr][0] = __dp4a((int)a[i].y, (int)b1.x, acc[rr][0]);
                        acc[rr][0] = __dp4a((int)a[i].z, (int)b2.x, acc[rr][0]);
                        acc[rr][0] = __dp4a((int)a[i].w, (int)b3.x, acc[rr][0]);
                        acc[rr][1] = __dp4a((int)a[i].x, (int)b0.y, acc[rr][1]);
                        acc[rr][1] = __dp4a((int)a[i].y, (int)b1.y, acc[rr][1]);
                        acc[rr][1] = __dp4a((int)a[i].z, (int)b2.y, acc[rr][1]);
                        acc[rr][1] = __dp4a((int)a[i].w, (int)b3.y, acc[rr][1]);
                        acc[rr][2] = __dp4a((int)a[i].x, (int)b0.z, acc[rr][2]);
                        acc[rr][2] = __dp4a((int)a[i].y, (int)b1.z, acc[rr][2]);
                        acc[rr][2] = __dp4a((int)a[i].z, (int)b2.z, acc[rr][2]);
                        acc[rr][2] = __dp4a((int)a[i].w, (int)b3.z, acc[rr][2]);
                        acc[rr][3] = __dp4a((int)a[i].x, (int)b0.w, acc[rr][3]);
                        acc[rr][3] = __dp4a((int)a[i].y, (int)b1.w, acc[rr][3]);
                        acc[rr][3] = __dp4a((int)a[i].z, (int)b2.w, acc[rr][3]);
                        acc[rr][3] = __dp4a((int)a[i].w, (int)b3.w, acc[rr][3]);
                    }
                }
            }
        }

        const int col0 = tile_n * BN + 64 + cx * 4;
        float4 bv;
        bv.x = __ldg(bias + col0 + 0);
        bv.y = __ldg(bias + col0 + 1);
        bv.z = __ldg(bias + col0 + 2);
        bv.w = __ldg(bias + col0 + 3);
#pragma unroll
        for (int i = 0; i < 16; ++i) {
            const int row = tile_m * BM + ry * 16 + i;
            const float inv = g_inv_scale[row];
            float4 r4;
            r4.x = (float)acc[i][0] * inv + bv.x;
            r4.y = (float)acc[i][1] * inv + bv.y;
            r4.z = (float)acc[i][2] * inv + bv.z;
            r4.w = (float)acc[i][3] * inv + bv.w;
            *reinterpret_cast<float4*>(out + (size_t)row * DOUT + col0) = r4;
        }
    }
}

// ============================================================================
// launch
// ============================================================================
extern "C" void kernel_launch(void* const* d_in, const int* in_sizes, int n_in,
                              void* d_out, int out_size) {
    (void)in_sizes; (void)n_in; (void)out_size;
    const float* x       = (const float*)d_in[0];
    const float* w       = (const float*)d_in[1];
    const float* scale_w = (const float*)d_in[2];
    const float* gamma   = (const float*)d_in[3];
    const float* bias    = (const float*)d_in[4];
    float* out = (float*)d_out;

    cudaFuncSetAttribute(gemm_hybrid_kernel, cudaFuncAttributeMaxDynamicSharedMemorySize,
                         SMEM_DYN_TOTAL);

    quant_fused_kernel<<<MTOK + WTBLOCKS, 256>>>(x, w, gamma, scale_w);
    gemm_hybrid_kernel<<<dim3(DOUT / BN, MTOK / BM), 256, SMEM_DYN_TOTAL>>>(bias, out);
}